// round 10
// baseline (speedup 1.0000x reference)
#include <cuda_runtime.h>
#include <cuda_fp16.h>
#include <math.h>
#include <stdint.h>

#define T_TOK 8192
#define HID   7168
#define NEXP  256

// ---- scratch ----
__device__ float  g_scores[(size_t)T_TOK * NEXP];            // 8 MB
__device__ __half g_xh[(size_t)T_TOK * HID];                 // 117 MB
__device__ __half g_xl[(size_t)T_TOK * HID];                 // 117 MB
__device__ __half g_wh[(size_t)NEXP * HID];                  // 3.7 MB
__device__ __half g_wl[(size_t)NEXP * HID];                  // 3.7 MB
__device__ int    g_nflag;
__device__ int    g_flags[T_TOK];

#define THETA   2e-5f
#define MARG_T  (3.0f * THETA)
#define MARG_G  (8.0f * THETA)

// ============================ helpers ============================
__device__ __forceinline__ uint32_t smem_u32(const void* p) {
    uint32_t a;
    asm("{ .reg .u64 t; cvta.to.shared.u64 t, %1; cvt.u32.u64 %0, t; }" : "=r"(a) : "l"(p));
    return a;
}
__device__ __forceinline__ void cpa16(uint32_t dst, const void* src) {
    asm volatile("cp.async.cg.shared.global [%0], [%1], 16;" :: "r"(dst), "l"(src));
}
#define CP_COMMIT() asm volatile("cp.async.commit_group;")
#define CP_WAIT1()  asm volatile("cp.async.wait_group 1;")

#define MMAH(d, a, b) asm volatile( \
    "mma.sync.aligned.m16n8k16.row.col.f32.f16.f16.f32 " \
    "{%0,%1,%2,%3}, {%4,%5,%6,%7}, {%8,%9}, {%0,%1,%2,%3};" \
    : "+f"((d)[0]), "+f"((d)[1]), "+f"((d)[2]), "+f"((d)[3]) \
    : "r"((a)[0]), "r"((a)[1]), "r"((a)[2]), "r"((a)[3]), \
      "r"((b)[0]), "r"((b)[1]))

__device__ __forceinline__ uint32_t pack_h2(__half a, __half b) {
    __half2 h2 = __halves2half2(a, b);
    __half2_raw r = *reinterpret_cast<__half2_raw*>(&h2);
    return (uint32_t)r.x | ((uint32_t)r.y << 16);
}

// ============================================================================
// K0: split fp32 tensor into fp16 hi/lo planes (round-to-nearest both)
// ============================================================================
__global__ __launch_bounds__(256) void split_kernel(
    const float* __restrict__ src, __half* __restrict__ dh,
    __half* __restrict__ dl, size_t n4)   // n4 = count of float4
{
    size_t i = (size_t)blockIdx.x * blockDim.x + threadIdx.x;
    size_t stride = (size_t)gridDim.x * blockDim.x;
    for (; i < n4; i += stride) {
        float4 f = ((const float4*)src)[i];
        __half h0 = __float2half_rn(f.x), h1 = __float2half_rn(f.y);
        __half h2 = __float2half_rn(f.z), h3 = __float2half_rn(f.w);
        __half l0 = __float2half_rn(f.x - __half2float(h0));
        __half l1 = __float2half_rn(f.y - __half2float(h1));
        __half l2 = __float2half_rn(f.z - __half2float(h2));
        __half l3 = __float2half_rn(f.w - __half2float(h3));
        uint2 ph = make_uint2(pack_h2(h0, h1), pack_h2(h2, h3));
        uint2 pl = make_uint2(pack_h2(l0, l1), pack_h2(l2, l3));
        ((uint2*)dh)[i] = ph;
        ((uint2*)dl)[i] = pl;
    }
}

// ============================ K1 config ============================
constexpr int BM = 128, BN = 128, BK = 64;      // BK in halves
constexpr int NCHUNK = HID / BK;                // 112
constexpr int RS = 36;                          // u32 row stride (32 data + 4 pad)
constexpr int TILE_U = 128 * RS;                // 4608 u32 = 18 KB
constexpr int STAGE_U = 4 * TILE_U;             // Ah Al Bh Bl = 72 KB
constexpr int NSTAGE = 3;
constexpr int SMEM_BYTES = NSTAGE * STAGE_U * 4;  // 221184 = 216 KB

// ============================================================================
// K1: pure fp16 3-pass GEMM from pre-split planes; sigmoid epilogue
// ============================================================================
__global__ __launch_bounds__(256, 1) void gemm_f16_kernel()
{
    extern __shared__ uint32_t smem[];
    const uint32_t sbase = smem_u32(smem);

    const int tid  = threadIdx.x;
    const int lane = tid & 31;
    const int wid  = tid >> 5;
    const int g    = lane >> 2;
    const int tg   = lane & 3;

    const int n0 = (blockIdx.x & 1) * BN;
    const int m0 = (blockIdx.x >> 1) * BM;
    const int wm = (wid & 1) * 64;
    const int wn = (wid >> 1) * 32;

    // cp.async mapping: thread covers row tid>>1, halves (tid&1)*32 + q*8
    const int lrow  = tid >> 1;
    const int lhalf = tid & 1;
    const __half* gah = g_xh + (size_t)(m0 + lrow) * HID + lhalf * 32;
    const __half* gal = g_xl + (size_t)(m0 + lrow) * HID + lhalf * 32;
    const __half* gbh = g_wh + (size_t)(n0 + lrow) * HID + lhalf * 32;
    const __half* gbl = g_wl + (size_t)(n0 + lrow) * HID + lhalf * 32;
    const uint32_t sdst = sbase + (uint32_t)(lrow * RS + lhalf * 16) * 4u;

    auto issue = [&](int c) {
        const int s = c % NSTAGE;
        const uint32_t d0 = sdst + (uint32_t)(s * STAGE_U) * 4u;
        const int ko = c * BK;
#pragma unroll
        for (int q = 0; q < 4; ++q) {
            cpa16(d0 + 0 * TILE_U * 4 + q * 16, gah + ko + q * 8);
            cpa16(d0 + 1 * TILE_U * 4 + q * 16, gal + ko + q * 8);
            cpa16(d0 + 2 * TILE_U * 4 + q * 16, gbh + ko + q * 8);
            cpa16(d0 + 3 * TILE_U * 4 + q * 16, gbl + ko + q * 8);
        }
    };

    issue(0); CP_COMMIT();
    issue(1); CP_COMMIT();

    float acc[4][4][4];
#pragma unroll
    for (int i = 0; i < 4; ++i)
#pragma unroll
        for (int j = 0; j < 4; ++j)
#pragma unroll
            for (int e = 0; e < 4; ++e) acc[i][j][e] = 0.f;

#pragma unroll 1
    for (int c = 0; c < NCHUNK; ++c) {
        CP_WAIT1();           // stage c resident (c+1 may be in flight)
        __syncthreads();      // also guarantees stage (c+2)%3 fully consumed
        if (c + 2 < NCHUNK) { issue(c + 2); CP_COMMIT(); }

        const uint32_t* Ah = smem + (c % NSTAGE) * STAGE_U;
        const uint32_t* Al = Ah + TILE_U;
        const uint32_t* Bh = Ah + 2 * TILE_U;
        const uint32_t* Bl = Ah + 3 * TILE_U;

#pragma unroll
        for (int kk = 0; kk < 4; ++kk) {
            const int kb = kk * 8 + tg;
            uint32_t ah[4][4], al[4][4], bh[4][2], bl[4][2];
#pragma unroll
            for (int i = 0; i < 4; ++i) {
                const int r0 = (wm + i * 16 + g) * RS;
                const int r1 = (wm + i * 16 + g + 8) * RS;
                ah[i][0] = Ah[r0 + kb];     ah[i][1] = Ah[r1 + kb];
                ah[i][2] = Ah[r0 + kb + 4]; ah[i][3] = Ah[r1 + kb + 4];
                al[i][0] = Al[r0 + kb];     al[i][1] = Al[r1 + kb];
                al[i][2] = Al[r0 + kb + 4]; al[i][3] = Al[r1 + kb + 4];
            }
#pragma unroll
            for (int j = 0; j < 4; ++j) {
                const int rn = (wn + j * 8 + g) * RS;
                bh[j][0] = Bh[rn + kb]; bh[j][1] = Bh[rn + kb + 4];
                bl[j][0] = Bl[rn + kb]; bl[j][1] = Bl[rn + kb + 4];
            }
#pragma unroll
            for (int i = 0; i < 4; ++i)
#pragma unroll
                for (int j = 0; j < 4; ++j) {
                    MMAH(acc[i][j], ah[i], bh[j]);
                    MMAH(acc[i][j], ah[i], bl[j]);
                    MMAH(acc[i][j], al[i], bh[j]);
                }
        }
    }

    // epilogue: sigmoid + store
#pragma unroll
    for (int i = 0; i < 4; ++i) {
        const int r0 = m0 + wm + i * 16 + g;
#pragma unroll
        for (int j = 0; j < 4; ++j) {
            float* p0 = g_scores + (size_t)r0 * NEXP + n0 + wn + j * 8 + tg * 2;
            float* p1 = p0 + 8 * NEXP;
            float2 v0, v1;
            v0.x = 1.f / (1.f + expf(-acc[i][j][0]));
            v0.y = 1.f / (1.f + expf(-acc[i][j][1]));
            v1.x = 1.f / (1.f + expf(-acc[i][j][2]));
            v1.y = 1.f / (1.f + expf(-acc[i][j][3]));
            *(float2*)p0 = v0;
            *(float2*)p1 = v1;
        }
    }
}

// ============================================================================
__global__ void reset_kernel() { g_nflag = 0; }

// ============================================================================
// K2: gate on approx scores with margin checks; flag tight tokens
// ============================================================================
__global__ __launch_bounds__(256) void gate_margin_kernel(
    const float* __restrict__ bias,
    float* __restrict__ out, int out_size)
{
    const int wid = threadIdx.x >> 5;
    const int l   = threadIdx.x & 31;
    const int t   = blockIdx.x * 8 + wid;

    const float* srow = g_scores + (size_t)t * NEXP;
    float v[8];
#pragma unroll
    for (int k = 0; k < 8; ++k)
        v[k] = srow[k * 32 + l] + bias[k * 32 + l];

    float gsc[8];
#pragma unroll
    for (int k = 0; k < 8; ++k) {
        float m1 = v[k];
#pragma unroll
        for (int o = 16; o > 0; o >>= 1) m1 = fmaxf(m1, __shfl_xor_sync(0xffffffffu, m1, o));
        unsigned bal = __ballot_sync(0xffffffffu, v[k] == m1);
        int fl = __ffs(bal) - 1;
        float vx = (l == fl) ? -INFINITY : v[k];
#pragma unroll
        for (int o = 16; o > 0; o >>= 1) vx = fmaxf(vx, __shfl_xor_sync(0xffffffffu, vx, o));
        gsc[k] = m1 + vx;
    }

    unsigned keep = 0;
    float g4 = INFINITY;
#pragma unroll
    for (int r = 0; r < 4; ++r) {
        float best = -INFINITY; int bi = 0;
#pragma unroll
        for (int k = 0; k < 8; ++k) {
            bool tk = !((keep >> k) & 1u) && (gsc[k] > best);
            best = tk ? gsc[k] : best;
            bi   = tk ? k : bi;
        }
        keep |= 1u << bi;
        g4 = best;
    }
    float g5 = -INFINITY;
#pragma unroll
    for (int k = 0; k < 8; ++k)
        if (!((keep >> k) & 1u)) g5 = fmaxf(g5, gsc[k]);

    bool flag = (g4 - g5) < MARG_G;

    float cand[8];
#pragma unroll
    for (int k = 0; k < 8; ++k) cand[k] = ((keep >> k) & 1u) ? v[k] : -INFINITY;

    float sval[9]; int sel[9];
#pragma unroll
    for (int r = 0; r < 9; ++r) {
        float bv = cand[0]; int bk = 0;
#pragma unroll
        for (int k = 1; k < 8; ++k) {
            bool tk = cand[k] > bv;
            bv = tk ? cand[k] : bv;
            bk = tk ? k : bk;
        }
        int be = bk * 32 + l;
#pragma unroll
        for (int o = 16; o > 0; o >>= 1) {
            float ov = __shfl_xor_sync(0xffffffffu, bv, o);
            int   oe = __shfl_xor_sync(0xffffffffu, be, o);
            if (ov > bv || (ov == bv && oe < be)) { bv = ov; be = oe; }
        }
        sval[r] = bv; sel[r] = be;
        const int kk = be >> 5, ll = be & 31;
#pragma unroll
        for (int k = 0; k < 8; ++k)
            if (k == kk && l == ll) cand[k] = -INFINITY;
    }
#pragma unroll
    for (int r = 0; r < 8; ++r)
        flag = flag || ((sval[r] - sval[r + 1]) < MARG_T);

    if (l == 0) {
        if (flag) {
            int idx = atomicAdd(&g_nflag, 1);
            g_flags[idx] = t;
        }
        float wv[8], sw = 0.f;
#pragma unroll
        for (int r = 0; r < 8; ++r) { wv[r] = srow[sel[r]]; sw += wv[r]; }
        const float inv = 2.5f / (sw + 1e-20f);
        float4 w0 = make_float4(wv[0] * inv, wv[1] * inv, wv[2] * inv, wv[3] * inv);
        float4 w1 = make_float4(wv[4] * inv, wv[5] * inv, wv[6] * inv, wv[7] * inv);
        float4* wo = (float4*)(out + (size_t)t * 8);
        wo[0] = w0; wo[1] = w1;
        if (out_size >= 2 * T_TOK * 8) {
            float4 i0 = make_float4((float)sel[0], (float)sel[1], (float)sel[2], (float)sel[3]);
            float4 i1 = make_float4((float)sel[4], (float)sel[5], (float)sel[6], (float)sel[7]);
            float4* io = (float4*)(out + (size_t)T_TOK * 8 + (size_t)t * 8);
            io[0] = i0; io[1] = i1;
        }
    }
}

// ============================================================================
// K3: exact serial recompute + gate for flagged tokens (ascending-k chain)
// ============================================================================
__global__ __launch_bounds__(256) void fixup_kernel(
    const float* __restrict__ x, const float* __restrict__ w,
    const float* __restrict__ bias,
    float* __restrict__ out, int out_size)
{
    __shared__ float xs[HID];
    __shared__ float ss[NEXP];

    const int tid = threadIdx.x;
    const int nflag = g_nflag;

    for (int fi = blockIdx.x; fi < nflag; fi += gridDim.x) {
        const int t = g_flags[fi];

        for (int i = tid; i < HID; i += 256)
            xs[i] = x[(size_t)t * HID + i];
        __syncthreads();

        {
            const float4* wr = (const float4*)(w + (size_t)tid * HID);
            float acc = 0.f;
#pragma unroll 8
            for (int q = 0; q < HID / 4; ++q) {
                float4 f = wr[q];
                const float* xq = xs + q * 4;
                acc = fmaf(xq[0], f.x, acc);
                acc = fmaf(xq[1], f.y, acc);
                acc = fmaf(xq[2], f.z, acc);
                acc = fmaf(xq[3], f.w, acc);
            }
            ss[tid] = 1.f / (1.f + expf(-acc));
        }
        __syncthreads();

        if (tid < 32) {
            const int l = tid;
            float v[8];
#pragma unroll
            for (int k = 0; k < 8; ++k)
                v[k] = ss[k * 32 + l] + bias[k * 32 + l];

            float gsc[8];
#pragma unroll
            for (int k = 0; k < 8; ++k) {
                float m1 = v[k];
#pragma unroll
                for (int o = 16; o > 0; o >>= 1) m1 = fmaxf(m1, __shfl_xor_sync(0xffffffffu, m1, o));
                unsigned bal = __ballot_sync(0xffffffffu, v[k] == m1);
                int fl = __ffs(bal) - 1;
                float vx = (l == fl) ? -INFINITY : v[k];
#pragma unroll
                for (int o = 16; o > 0; o >>= 1) vx = fmaxf(vx, __shfl_xor_sync(0xffffffffu, vx, o));
                gsc[k] = m1 + vx;
            }
            unsigned keep = 0;
#pragma unroll
            for (int r = 0; r < 4; ++r) {
                float best = -INFINITY; int bi = 0;
#pragma unroll
                for (int k = 0; k < 8; ++k) {
                    bool tk = !((keep >> k) & 1u) && (gsc[k] > best);
                    best = tk ? gsc[k] : best;
                    bi   = tk ? k : bi;
                }
                keep |= 1u << bi;
            }
            float cand[8];
#pragma unroll
            for (int k = 0; k < 8; ++k) cand[k] = ((keep >> k) & 1u) ? v[k] : -INFINITY;

            int sel[8]; float wv[8];
#pragma unroll
            for (int r = 0; r < 8; ++r) {
                float bv = cand[0]; int bk = 0;
#pragma unroll
                for (int k = 1; k < 8; ++k) {
                    bool tk = cand[k] > bv;
                    bv = tk ? cand[k] : bv;
                    bk = tk ? k : bk;
                }
                int be = bk * 32 + l;
#pragma unroll
                for (int o = 16; o > 0; o >>= 1) {
                    float ov = __shfl_xor_sync(0xffffffffu, bv, o);
                    int   oe = __shfl_xor_sync(0xffffffffu, be, o);
                    if (ov > bv || (ov == bv && oe < be)) { bv = ov; be = oe; }
                }
                sel[r] = be;
                const int kk = be >> 5, ll = be & 31;
#pragma unroll
                for (int k = 0; k < 8; ++k)
                    if (k == kk && l == ll) cand[k] = -INFINITY;
            }
            if (l == 0) {
                float sw = 0.f;
#pragma unroll
                for (int r = 0; r < 8; ++r) { wv[r] = ss[sel[r]]; sw += wv[r]; }
                const float inv = 2.5f / (sw + 1e-20f);
                float* wo = out + (size_t)t * 8;
#pragma unroll
                for (int r = 0; r < 8; ++r) wo[r] = wv[r] * inv;
                if (out_size >= 2 * T_TOK * 8) {
                    float* io = out + (size_t)T_TOK * 8 + (size_t)t * 8;
#pragma unroll
                    for (int r = 0; r < 8; ++r) io[r] = (float)sel[r];
                }
            }
        }
        __syncthreads();
    }
}

// ============================================================================
extern "C" void kernel_launch(void* const* d_in, const int* in_sizes, int n_in,
                              void* d_out, int out_size)
{
    const float* x = nullptr; const float* w = nullptr; const float* b = nullptr;
    for (int i = 0; i < n_in; ++i) {
        long long sz = in_sizes[i];
        if (sz == (long long)T_TOK * HID) x = (const float*)d_in[i];
        else if (sz == (long long)NEXP * HID) w = (const float*)d_in[i];
        else if (sz == NEXP) b = (const float*)d_in[i];
    }
    float* out = (float*)d_out;

    cudaFuncSetAttribute(gemm_f16_kernel,
                         cudaFuncAttributeMaxDynamicSharedMemorySize, SMEM_BYTES);

    __half *xh, *xl, *wh, *wl;
    cudaGetSymbolAddress((void**)&xh, g_xh);
    cudaGetSymbolAddress((void**)&xl, g_xl);
    cudaGetSymbolAddress((void**)&wh, g_wh);
    cudaGetSymbolAddress((void**)&wl, g_wl);

    reset_kernel<<<1, 1>>>();
    split_kernel<<<2048, 256>>>(x, xh, xl, (size_t)T_TOK * HID / 4);
    split_kernel<<<64, 256>>>(w, wh, wl, (size_t)NEXP * HID / 4);
    gemm_f16_kernel<<<(T_TOK / BM) * (NEXP / BN), 256, SMEM_BYTES>>>();
    gate_margin_kernel<<<T_TOK / 8, 256>>>(b, out, out_size);
    fixup_kernel<<<256, 256>>>(x, w, b, out, out_size);
}

// round 11
// speedup vs baseline: 1.0299x; 1.0299x over previous
#include <cuda_runtime.h>
#include <cuda_fp16.h>
#include <math.h>
#include <stdint.h>

#define T_TOK 8192
#define HID   7168
#define NEXP  256

// ---- scratch ----
__device__ float  g_part[2][(size_t)T_TOK * NEXP];           // 16 MB partial logits
__device__ __half g_xh[(size_t)T_TOK * HID];
__device__ __half g_xl[(size_t)T_TOK * HID];
__device__ __half g_wh[(size_t)NEXP * HID];
__device__ __half g_wl[(size_t)NEXP * HID];
__device__ int    g_nflag;
__device__ int    g_flags[T_TOK];

#define THETA   2e-5f
#define MARG_T  (3.0f * THETA)
#define MARG_G  (8.0f * THETA)

// ============================ helpers ============================
__device__ __forceinline__ uint32_t smem_u32(const void* p) {
    uint32_t a;
    asm("{ .reg .u64 t; cvta.to.shared.u64 t, %1; cvt.u32.u64 %0, t; }" : "=r"(a) : "l"(p));
    return a;
}
__device__ __forceinline__ void cpa16(uint32_t dst, const void* src) {
    asm volatile("cp.async.cg.shared.global [%0], [%1], 16;" :: "r"(dst), "l"(src));
}
#define CP_COMMIT() asm volatile("cp.async.commit_group;")
#define CP_WAIT0()  asm volatile("cp.async.wait_group 0;")

#define MMAH(d, a, b) asm volatile( \
    "mma.sync.aligned.m16n8k16.row.col.f32.f16.f16.f32 " \
    "{%0,%1,%2,%3}, {%4,%5,%6,%7}, {%8,%9}, {%0,%1,%2,%3};" \
    : "+f"((d)[0]), "+f"((d)[1]), "+f"((d)[2]), "+f"((d)[3]) \
    : "r"((a)[0]), "r"((a)[1]), "r"((a)[2]), "r"((a)[3]), \
      "r"((b)[0]), "r"((b)[1]))

__device__ __forceinline__ uint32_t pack_h2(__half a, __half b) {
    __half2 h2 = __halves2half2(a, b);
    __half2_raw r = *reinterpret_cast<__half2_raw*>(&h2);
    return (uint32_t)r.x | ((uint32_t)r.y << 16);
}

// ============================================================================
// K0: split fp32 -> fp16 hi/lo planes. Exact grid; 8 floats/thread; 16B stores.
// ============================================================================
__global__ __launch_bounds__(256) void split_kernel(
    const float* __restrict__ src, __half* __restrict__ dh,
    __half* __restrict__ dl)
{
    const size_t i = (size_t)blockIdx.x * 256 + threadIdx.x;  // 8-float unit
    const float4 f0 = ((const float4*)src)[2 * i];
    const float4 f1 = ((const float4*)src)[2 * i + 1];

    __half h[8], l[8];
    const float* f = &f0.x;
#pragma unroll
    for (int e = 0; e < 8; ++e) {
        float v = (e < 4) ? (&f0.x)[e] : (&f1.x)[e - 4];
        h[e] = __float2half_rn(v);
        l[e] = __float2half_rn(v - __half2float(h[e]));
    }
    (void)f;
    uint4 uh = make_uint4(pack_h2(h[0], h[1]), pack_h2(h[2], h[3]),
                          pack_h2(h[4], h[5]), pack_h2(h[6], h[7]));
    uint4 ul = make_uint4(pack_h2(l[0], l[1]), pack_h2(l[2], l[3]),
                          pack_h2(l[4], l[5]), pack_h2(l[6], l[7]));
    ((uint4*)dh)[i] = uh;
    ((uint4*)dl)[i] = ul;
}

// ============================ K1 config ============================
constexpr int BM = 128, BN = 128, BK = 32;      // BK in halves
constexpr int KSPLIT = 2;
constexpr int KHALF  = HID / KSPLIT;            // 3584
constexpr int NCHUNK = KHALF / BK;              // 112
constexpr int RS = 20;                          // u32 row stride (16 data + 4 pad)
constexpr int TILE_U = 128 * RS;                // 2560 u32 = 10 KB
constexpr int STAGE_U = 4 * TILE_U;             // Ah Al Bh Bl = 40 KB
constexpr int NSTAGE = 2;
constexpr int SMEM_BYTES = NSTAGE * STAGE_U * 4;  // 81920

// ============================================================================
// K1: fp16 3-pass GEMM, split-K x2, raw partial logits out. 2 CTAs/SM.
// ============================================================================
__global__ __launch_bounds__(256, 2) void gemm_f16_kernel()
{
    extern __shared__ uint32_t smem[];

    const int tid  = threadIdx.x;
    const int lane = tid & 31;
    const int wid  = tid >> 5;
    const int g    = lane >> 2;
    const int tg   = lane & 3;

    const int ks = blockIdx.x >> 7;             // 0/1 k-split
    const int r  = blockIdx.x & 127;
    const int n0 = (r & 1) * BN;
    const int m0 = (r >> 1) * BM;
    const int wm = (wid & 1) * 64;
    const int wn = (wid >> 1) * 32;
    const int k0 = ks * KHALF;

    // cp.async mapping: row tid>>1, 16B-pair (tid&1)
    const int lrow  = tid >> 1;
    const int lhalf = tid & 1;                  // 0/1 -> halves offset 0/16
    const __half* gah = g_xh + (size_t)(m0 + lrow) * HID + k0 + lhalf * 16;
    const __half* gal = g_xl + (size_t)(m0 + lrow) * HID + k0 + lhalf * 16;
    const __half* gbh = g_wh + (size_t)(n0 + lrow) * HID + k0 + lhalf * 16;
    const __half* gbl = g_wl + (size_t)(n0 + lrow) * HID + k0 + lhalf * 16;
    const uint32_t sbase = smem_u32(smem);
    const uint32_t sdst = sbase + (uint32_t)(lrow * RS + lhalf * 8) * 4u;

    auto issue = [&](int c) {
        const uint32_t d0 = sdst + (uint32_t)((c & 1) * STAGE_U) * 4u;
        const int ko = c * BK;
        cpa16(d0 + 0 * TILE_U * 4 + 0,  gah + ko);
        cpa16(d0 + 0 * TILE_U * 4 + 16, gah + ko + 8);
        cpa16(d0 + 1 * TILE_U * 4 + 0,  gal + ko);
        cpa16(d0 + 1 * TILE_U * 4 + 16, gal + ko + 8);
        cpa16(d0 + 2 * TILE_U * 4 + 0,  gbh + ko);
        cpa16(d0 + 2 * TILE_U * 4 + 16, gbh + ko + 8);
        cpa16(d0 + 3 * TILE_U * 4 + 0,  gbl + ko);
        cpa16(d0 + 3 * TILE_U * 4 + 16, gbl + ko + 8);
    };

    issue(0); CP_COMMIT();

    float acc[4][4][4];
#pragma unroll
    for (int i = 0; i < 4; ++i)
#pragma unroll
        for (int j = 0; j < 4; ++j)
#pragma unroll
            for (int e = 0; e < 4; ++e) acc[i][j][e] = 0.f;

#pragma unroll 1
    for (int c = 0; c < NCHUNK; ++c) {
        CP_WAIT0();            // stage c&1 resident
        __syncthreads();       // all warps done consuming stage (c+1)&1
        if (c + 1 < NCHUNK) { issue(c + 1); CP_COMMIT(); }

        const uint32_t* Ah = smem + (c & 1) * STAGE_U;
        const uint32_t* Al = Ah + TILE_U;
        const uint32_t* Bh = Ah + 2 * TILE_U;
        const uint32_t* Bl = Ah + 3 * TILE_U;

#pragma unroll
        for (int kk = 0; kk < 2; ++kk) {
            const int kb = kk * 8 + tg;
            uint32_t ah[4][4], al[4][4], bh[4][2], bl[4][2];
#pragma unroll
            for (int i = 0; i < 4; ++i) {
                const int r0 = (wm + i * 16 + g) * RS;
                const int r1 = (wm + i * 16 + g + 8) * RS;
                ah[i][0] = Ah[r0 + kb];     ah[i][1] = Ah[r1 + kb];
                ah[i][2] = Ah[r0 + kb + 4]; ah[i][3] = Ah[r1 + kb + 4];
                al[i][0] = Al[r0 + kb];     al[i][1] = Al[r1 + kb];
                al[i][2] = Al[r0 + kb + 4]; al[i][3] = Al[r1 + kb + 4];
            }
#pragma unroll
            for (int j = 0; j < 4; ++j) {
                const int rn = (wn + j * 8 + g) * RS;
                bh[j][0] = Bh[rn + kb]; bh[j][1] = Bh[rn + kb + 4];
                bl[j][0] = Bl[rn + kb]; bl[j][1] = Bl[rn + kb + 4];
            }
#pragma unroll
            for (int i = 0; i < 4; ++i)
#pragma unroll
                for (int j = 0; j < 4; ++j) {
                    MMAH(acc[i][j], ah[i], bh[j]);
                    MMAH(acc[i][j], ah[i], bl[j]);
                    MMAH(acc[i][j], al[i], bh[j]);
                }
        }
    }

    // epilogue: raw partial logits
    float* plane = g_part[ks];
#pragma unroll
    for (int i = 0; i < 4; ++i) {
        const int r0 = m0 + wm + i * 16 + g;
#pragma unroll
        for (int j = 0; j < 4; ++j) {
            float* p0 = plane + (size_t)r0 * NEXP + n0 + wn + j * 8 + tg * 2;
            float* p1 = p0 + 8 * NEXP;
            *(float2*)p0 = make_float2(acc[i][j][0], acc[i][j][1]);
            *(float2*)p1 = make_float2(acc[i][j][2], acc[i][j][3]);
        }
    }
}

// ============================================================================
__global__ void reset_kernel() { g_nflag = 0; }

// ============================================================================
// K2: sum partials, sigmoid, margin-checked gate; flag tight tokens
// ============================================================================
__global__ __launch_bounds__(256) void gate_margin_kernel(
    const float* __restrict__ bias,
    float* __restrict__ out, int out_size)
{
    const int wid = threadIdx.x >> 5;
    const int l   = threadIdx.x & 31;
    const int t   = blockIdx.x * 8 + wid;

    const float* p0 = g_part[0] + (size_t)t * NEXP;
    const float* p1 = g_part[1] + (size_t)t * NEXP;
    float s[8], v[8];
#pragma unroll
    for (int k = 0; k < 8; ++k) {
        float logit = p0[k * 32 + l] + p1[k * 32 + l];
        s[k] = 1.f / (1.f + expf(-logit));
        v[k] = s[k] + bias[k * 32 + l];
    }

    float gsc[8];
#pragma unroll
    for (int k = 0; k < 8; ++k) {
        float m1 = v[k];
#pragma unroll
        for (int o = 16; o > 0; o >>= 1) m1 = fmaxf(m1, __shfl_xor_sync(0xffffffffu, m1, o));
        unsigned bal = __ballot_sync(0xffffffffu, v[k] == m1);
        int fl = __ffs(bal) - 1;
        float vx = (l == fl) ? -INFINITY : v[k];
#pragma unroll
        for (int o = 16; o > 0; o >>= 1) vx = fmaxf(vx, __shfl_xor_sync(0xffffffffu, vx, o));
        gsc[k] = m1 + vx;
    }

    unsigned keep = 0;
    float g4 = INFINITY;
#pragma unroll
    for (int r = 0; r < 4; ++r) {
        float best = -INFINITY; int bi = 0;
#pragma unroll
        for (int k = 0; k < 8; ++k) {
            bool tk = !((keep >> k) & 1u) && (gsc[k] > best);
            best = tk ? gsc[k] : best;
            bi   = tk ? k : bi;
        }
        keep |= 1u << bi;
        g4 = best;
    }
    float g5 = -INFINITY;
#pragma unroll
    for (int k = 0; k < 8; ++k)
        if (!((keep >> k) & 1u)) g5 = fmaxf(g5, gsc[k]);

    bool flag = (g4 - g5) < MARG_G;

    float cand[8];
#pragma unroll
    for (int k = 0; k < 8; ++k) cand[k] = ((keep >> k) & 1u) ? v[k] : -INFINITY;

    float sval[9]; int sel[9];
#pragma unroll
    for (int r = 0; r < 9; ++r) {
        float bv = cand[0]; int bk = 0;
#pragma unroll
        for (int k = 1; k < 8; ++k) {
            bool tk = cand[k] > bv;
            bv = tk ? cand[k] : bv;
            bk = tk ? k : bk;
        }
        int be = bk * 32 + l;
#pragma unroll
        for (int o = 16; o > 0; o >>= 1) {
            float ov = __shfl_xor_sync(0xffffffffu, bv, o);
            int   oe = __shfl_xor_sync(0xffffffffu, be, o);
            if (ov > bv || (ov == bv && oe < be)) { bv = ov; be = oe; }
        }
        sval[r] = bv; sel[r] = be;
        const int kk = be >> 5, ll = be & 31;
#pragma unroll
        for (int k = 0; k < 8; ++k)
            if (k == kk && l == ll) cand[k] = -INFINITY;
    }
#pragma unroll
    for (int r = 0; r < 8; ++r)
        flag = flag || ((sval[r] - sval[r + 1]) < MARG_T);

    // fetch original scores of selected experts via predicated select + shfl
    float wv[8];
#pragma unroll
    for (int r = 0; r < 8; ++r) {
        const int kk = sel[r] >> 5, ll = sel[r] & 31;
        float val = 0.f;
#pragma unroll
        for (int k = 0; k < 8; ++k)
            if (k == kk) val = s[k];
        wv[r] = __shfl_sync(0xffffffffu, val, ll);
    }

    if (l == 0) {
        if (flag) {
            int idx = atomicAdd(&g_nflag, 1);
            g_flags[idx] = t;
        }
        float sw = 0.f;
#pragma unroll
        for (int r = 0; r < 8; ++r) sw += wv[r];
        const float inv = 2.5f / (sw + 1e-20f);
        float4 w0 = make_float4(wv[0] * inv, wv[1] * inv, wv[2] * inv, wv[3] * inv);
        float4 w1 = make_float4(wv[4] * inv, wv[5] * inv, wv[6] * inv, wv[7] * inv);
        float4* wo = (float4*)(out + (size_t)t * 8);
        wo[0] = w0; wo[1] = w1;
        if (out_size >= 2 * T_TOK * 8) {
            float4 i0 = make_float4((float)sel[0], (float)sel[1], (float)sel[2], (float)sel[3]);
            float4 i1 = make_float4((float)sel[4], (float)sel[5], (float)sel[6], (float)sel[7]);
            float4* io = (float4*)(out + (size_t)T_TOK * 8 + (size_t)t * 8);
            io[0] = i0; io[1] = i1;
        }
    }
}

// ============================================================================
// K3: exact serial recompute + gate for flagged tokens (ascending-k chain)
// ============================================================================
__global__ __launch_bounds__(256) void fixup_kernel(
    const float* __restrict__ x, const float* __restrict__ w,
    const float* __restrict__ bias,
    float* __restrict__ out, int out_size)
{
    __shared__ float xs[HID];
    __shared__ float ss[NEXP];

    const int tid = threadIdx.x;
    const int nflag = g_nflag;

    for (int fi = blockIdx.x; fi < nflag; fi += gridDim.x) {
        const int t = g_flags[fi];

        for (int i = tid; i < HID; i += 256)
            xs[i] = x[(size_t)t * HID + i];
        __syncthreads();

        {
            const float4* wr = (const float4*)(w + (size_t)tid * HID);
            float acc = 0.f;
#pragma unroll 8
            for (int q = 0; q < HID / 4; ++q) {
                float4 f = wr[q];
                const float* xq = xs + q * 4;
                acc = fmaf(xq[0], f.x, acc);
                acc = fmaf(xq[1], f.y, acc);
                acc = fmaf(xq[2], f.z, acc);
                acc = fmaf(xq[3], f.w, acc);
            }
            ss[tid] = 1.f / (1.f + expf(-acc));
        }
        __syncthreads();

        if (tid < 32) {
            const int l = tid;
            float v[8];
#pragma unroll
            for (int k = 0; k < 8; ++k)
                v[k] = ss[k * 32 + l] + bias[k * 32 + l];

            float gsc[8];
#pragma unroll
            for (int k = 0; k < 8; ++k) {
                float m1 = v[k];
#pragma unroll
                for (int o = 16; o > 0; o >>= 1) m1 = fmaxf(m1, __shfl_xor_sync(0xffffffffu, m1, o));
                unsigned bal = __ballot_sync(0xffffffffu, v[k] == m1);
                int fl = __ffs(bal) - 1;
                float vx = (l == fl) ? -INFINITY : v[k];
#pragma unroll
                for (int o = 16; o > 0; o >>= 1) vx = fmaxf(vx, __shfl_xor_sync(0xffffffffu, vx, o));
                gsc[k] = m1 + vx;
            }
            unsigned keep = 0;
#pragma unroll
            for (int r = 0; r < 4; ++r) {
                float best = -INFINITY; int bi = 0;
#pragma unroll
                for (int k = 0; k < 8; ++k) {
                    bool tk = !((keep >> k) & 1u) && (gsc[k] > best);
                    best = tk ? gsc[k] : best;
                    bi   = tk ? k : bi;
                }
                keep |= 1u << bi;
            }
            float cand[8];
#pragma unroll
            for (int k = 0; k < 8; ++k) cand[k] = ((keep >> k) & 1u) ? v[k] : -INFINITY;

            int sel[8]; float wv[8];
#pragma unroll
            for (int r = 0; r < 8; ++r) {
                float bv = cand[0]; int bk = 0;
#pragma unroll
                for (int k = 1; k < 8; ++k) {
                    bool tk = cand[k] > bv;
                    bv = tk ? cand[k] : bv;
                    bk = tk ? k : bk;
                }
                int be = bk * 32 + l;
#pragma unroll
                for (int o = 16; o > 0; o >>= 1) {
                    float ov = __shfl_xor_sync(0xffffffffu, bv, o);
                    int   oe = __shfl_xor_sync(0xffffffffu, be, o);
                    if (ov > bv || (ov == bv && oe < be)) { bv = ov; be = oe; }
                }
                sel[r] = be;
                const int kk = be >> 5, ll = be & 31;
#pragma unroll
                for (int k = 0; k < 8; ++k)
                    if (k == kk && l == ll) cand[k] = -INFINITY;
            }
            if (l == 0) {
                float sw = 0.f;
#pragma unroll
                for (int r = 0; r < 8; ++r) { wv[r] = ss[sel[r]]; sw += wv[r]; }
                const float inv = 2.5f / (sw + 1e-20f);
                float* wo = out + (size_t)t * 8;
#pragma unroll
                for (int r = 0; r < 8; ++r) wo[r] = wv[r] * inv;
                if (out_size >= 2 * T_TOK * 8) {
                    float* io = out + (size_t)T_TOK * 8 + (size_t)t * 8;
#pragma unroll
                    for (int r = 0; r < 8; ++r) io[r] = (float)sel[r];
                }
            }
        }
        __syncthreads();
    }
}

// ============================================================================
extern "C" void kernel_launch(void* const* d_in, const int* in_sizes, int n_in,
                              void* d_out, int out_size)
{
    const float* x = nullptr; const float* w = nullptr; const float* b = nullptr;
    for (int i = 0; i < n_in; ++i) {
        long long sz = in_sizes[i];
        if (sz == (long long)T_TOK * HID) x = (const float*)d_in[i];
        else if (sz == (long long)NEXP * HID) w = (const float*)d_in[i];
        else if (sz == NEXP) b = (const float*)d_in[i];
    }
    float* out = (float*)d_out;

    cudaFuncSetAttribute(gemm_f16_kernel,
                         cudaFuncAttributeMaxDynamicSharedMemorySize, SMEM_BYTES);

    __half *xh, *xl, *wh, *wl;
    cudaGetSymbolAddress((void**)&xh, g_xh);
    cudaGetSymbolAddress((void**)&xl, g_xl);
    cudaGetSymbolAddress((void**)&wh, g_wh);
    cudaGetSymbolAddress((void**)&wl, g_wl);

    reset_kernel<<<1, 1>>>();
    split_kernel<<<(int)((size_t)T_TOK * HID / 8 / 256), 256>>>(x, xh, xl);
    split_kernel<<<(int)((size_t)NEXP * HID / 8 / 256), 256>>>(w, wh, wl);
    gemm_f16_kernel<<<128 * KSPLIT, 256, SMEM_BYTES>>>();
    gate_margin_kernel<<<T_TOK / 8, 256>>>(b, out, out_size);
    fixup_kernel<<<256, 256>>>(x, w, b, out, out_size);
}